// round 5
// baseline (speedup 1.0000x reference)
#include <cuda_runtime.h>

#define NT 1096
#define NS 2048
#define NH 16
#define UF 8            // unroll factor; NT = 8 * 137 exactly

__global__ __launch_bounds__(128)
void waternet_kernel(const float* __restrict__ P, const float* __restrict__ T,
                     const float* __restrict__ w_i, const float* __restrict__ w_o,
                     const float* __restrict__ w_l, const float* __restrict__ w_s,
                     float* __restrict__ Q, float* __restrict__ H, float* __restrict__ S)
{
    const int gid  = blockIdx.x * blockDim.x + threadIdx.x;   // site*NH + h
    const int site = gid >> 4;
    const int hidx = gid & 15;

    // Time-invariant gate factors
    const float melt = expf(w_s[hidx]) + 1.0f;
    const float gi   = 1.0f / (1.0f + expf(-w_i[hidx]));
    const float gl   = 1.0f / (1.0f + expf(-w_l[hidx]));

    float wmax = w_o[0];
    #pragma unroll
    for (int i = 1; i < NH; ++i) wmax = fmaxf(wmax, w_o[i]);
    float denom = 0.0f;
    #pragma unroll
    for (int i = 0; i < NH; ++i) denom += expf(w_o[i] - wmax);
    const float a = expf(w_o[hidx] - wmax) / denom;

    // Linear-bucket identity:  h_new = (1-gl)*(h + xin),  q = gl*(h + xin)
    //  => h_new = alpha*h + (alpha*gi)*x ;  q = (gl/alpha)*h_new
    const float alpha = 1.0f - gl;
    const float gax   = alpha * gi;            // multiplies raw snow output x
    const float c     = a * gl / alpha;        // q*a = h_new * c

    float s  = 0.0f;   // snow store
    float hs = 0.0f;   // linear-bucket store

    const float* Pp = P + site;
    const float* Tp = T + site;
    float* Hp = H + gid;
    float* Sp = S + gid;
    float* Qp = Q + site;

    const bool b3 = (hidx & 8) != 0;
    const bool b2 = (hidx & 4) != 0;
    const bool b1 = (hidx & 2) != 0;
    const bool qlane = (hidx & 1) == 0;
    const int  qidx  = hidx >> 1;              // timestep slot this lane finalizes

    // Double-buffered prefetch: load group g+1 while computing group g.
    float pb[UF], tb[UF];
    #pragma unroll
    for (int i = 0; i < UF; ++i) {
        pb[i] = Pp[(size_t)i * NS];
        tb[i] = Tp[(size_t)i * NS];
    }

    for (int t0 = 0; t0 < NT; t0 += UF) {
        float pc[UF], tc[UF];
        #pragma unroll
        for (int i = 0; i < UF; ++i) { pc[i] = pb[i]; tc[i] = tb[i]; }

        // Prefetch next group (16 independent LDGs in flight)
        if (t0 + UF < NT) {
            #pragma unroll
            for (int i = 0; i < UF; ++i) {
                pb[i] = Pp[(size_t)(t0 + UF + i) * NS];
                tb[i] = Tp[(size_t)(t0 + UF + i) * NS];
            }
        }

        float qa[UF];
        #pragma unroll
        for (int i = 0; i < UF; ++i) {
            const float Pk = pc[i];
            const float Tk = tc[i];

            // SnowBucket: m = min(sm, s); s' = (s - m) + pin; x = rain + m
            const float sm   = fmaxf(Tk, 0.0f) * melt;
            const float m    = fminf(sm, s);
            const float pin  = (Tk < 0.0f) ? Pk : 0.0f;
            const float rain = (Tk > 0.0f) ? Pk : 0.0f;
            s = (s - m) + pin;
            const float x = rain + m;

            // LinearBucket (fused)
            hs = alpha * hs + gax * x;

            const size_t off = (size_t)(t0 + i) * (NS * NH);
            Hp[off] = hs;
            Sp[off] = s;

            qa[i] = hs * c;
        }

        // Multi-value butterfly: reduce 8 values over 16 lanes with 8 SHFLs.
        // After the tree, lane pair {2i, 2i+1} of each 16-lane group holds sum_i.
        #pragma unroll
        for (int i = 0; i < 4; ++i) {
            const float send = b3 ? qa[i] : qa[i + 4];
            const float recv = __shfl_xor_sync(0xffffffffu, send, 8);
            const float keep = b3 ? qa[i + 4] : qa[i];
            qa[i] = keep + recv;
        }
        #pragma unroll
        for (int i = 0; i < 2; ++i) {
            const float send = b2 ? qa[i] : qa[i + 2];
            const float recv = __shfl_xor_sync(0xffffffffu, send, 4);
            const float keep = b2 ? qa[i + 2] : qa[i];
            qa[i] = keep + recv;
        }
        {
            const float send = b1 ? qa[0] : qa[1];
            const float recv = __shfl_xor_sync(0xffffffffu, send, 2);
            const float keep = b1 ? qa[1] : qa[0];
            qa[0] = keep + recv;
        }
        qa[0] += __shfl_xor_sync(0xffffffffu, qa[0], 1);

        if (qlane) Qp[(size_t)(t0 + qidx) * NS] = qa[0];
    }
}

extern "C" void kernel_launch(void* const* d_in, const int* in_sizes, int n_in,
                              void* d_out, int out_size) {
    const float* P   = (const float*)d_in[0];
    const float* T   = (const float*)d_in[1];
    const float* w_i = (const float*)d_in[2];
    const float* w_o = (const float*)d_in[3];
    const float* w_l = (const float*)d_in[4];
    const float* w_s = (const float*)d_in[5];

    float* out = (float*)d_out;
    float* Q = out;                                           // [NT, NS]
    float* H = out + (size_t)NT * NS;                         // [NT, NS, NH]
    float* S = out + (size_t)NT * NS + (size_t)NT * NS * NH;  // [NT, NS, NH]

    const int total = NS * NH;          // 32768 threads
    const int block = 128;
    const int grid  = total / block;    // 256 blocks
    waternet_kernel<<<grid, block>>>(P, T, w_i, w_o, w_l, w_s, Q, H, S);
}